// round 11
// baseline (speedup 1.0000x reference)
#include <cuda_runtime.h>
#include <cstdint>

// PureCascadedBitFFN: out[elem, j] = j-th bit (LSB=0) of
// k = ceil(distance[elem] - 0.5) (exact reduction of the sigmoid cascade).
//
// R1-R10: every STG-path variant is pinned at 23.04us steady state
// (= 5.9 TB/s DRAM, 74% of HBM3e spec; LSU/ALU/LTS all have headroom).
// This round tests the ONE untried drain path: TMA bulk stores.
// Each block computes a 2048-quad (32 KB) tile into smem, then issues a
// single cp.async.bulk (1D SMEM->GMEM, async proxy) - large monotone
// write bursts formed at SMEM instead of per-sector STG drain, probing
// whether HBM write-burst efficiency (not the path-independent LTS cap)
// can improve.

__global__ __launch_bounds__(256) void cascaded_bits_tma_kernel(
    const float* __restrict__ dist,
    float4* __restrict__ out)
{
    __shared__ float4 tile[2048];            // 32 KB staging
    const int tid  = threadIdx.x;
    const int base = blockIdx.x * 2048;      // first quad of this block

    // Compute 8 quads per thread into smem (conflict-free STS.128:
    // consecutive lanes -> consecutive 16B words).
    #pragma unroll
    for (int i = 0; i < 8; i++) {
        const int lq = tid + i * 256;        // local quad in [0, 2048)
        const int q  = base + lq;
        const float r = __ldg(&dist[q >> 2]);
        const int k = __float2int_ru(r - 0.5f);   // exact round-half-down
        const int bit = (q & 3) << 2;        // starting bit: 0,4,8,12
        float4 v;
        v.x = __int_as_float(((k >> (bit + 0)) & 1) * 0x3F800000);
        v.y = __int_as_float(((k >> (bit + 1)) & 1) * 0x3F800000);
        v.z = __int_as_float(((k >> (bit + 2)) & 1) * 0x3F800000);
        v.w = __int_as_float(((k >> (bit + 3)) & 1) * 0x3F800000);
        tile[lq] = v;
    }
    __syncthreads();

    // Order generic-proxy smem writes before the async-proxy bulk read.
    asm volatile("fence.proxy.async.shared::cta;" ::: "memory");

    if (tid == 0) {
        uint32_t saddr;
        asm("{ .reg .u64 t; cvta.to.shared.u64 t, %1; cvt.u32.u64 %0, t; }"
            : "=r"(saddr) : "l"(tile));
        // Single 32 KB bulk store: SMEM -> GMEM through the async proxy.
        asm volatile(
            "cp.async.bulk.global.shared::cta.bulk_group [%0], [%1], %2;"
            :: "l"(out + base), "r"(saddr), "n"(32768) : "memory");
        asm volatile("cp.async.bulk.commit_group;" ::: "memory");
        // Must complete before smem is released at block exit.
        asm volatile("cp.async.bulk.wait_group.read 0;" ::: "memory");
    }
}

extern "C" void kernel_launch(void* const* d_in, const int* in_sizes, int n_in,
                              void* d_out, int out_size)
{
    const float* dist = (const float*)d_in[0];
    float4* out = (float4*)d_out;

    int n_elems = in_sizes[0];            // 512*4096 = 2,097,152
    int nquads  = n_elems * 4;            // 8,388,608
    int blocks  = nquads / 2048;          // 4096 (exact)

    cascaded_bits_tma_kernel<<<blocks, 256>>>(dist, out);
}